// round 13
// baseline (speedup 1.0000x reference)
#include <cuda_runtime.h>
#include <cuda_fp16.h>
#include <cstdint>

// Problem-shape upper bounds (N=100000, E=1600000 for this dataset).
#define NMAX 100000
#define EMAX 1600000
#define STILE 4096  // scan tile: 1024 threads x int4
#define NBINS 2048  // degree bins * 8 sub-bins (contention spreading)

// ---------------- scratch (static device globals) ---------------------------
__device__ __align__(16) __half g_h1h[(size_t)NMAX * 128];   // layer1 features (fp16)
__device__ __align__(16) __half g_h2h[(size_t)NMAX * 128];   // layer2 features (fp16)
__device__ __align__(16) __half g_out1h[(size_t)NMAX * 128]; // relu(gat1+b1) (fp16)
__device__ float4 g_asrc1[NMAX];
__device__ float4 g_adst1[NMAX];
__device__ float4 g_asrc2[NMAX];
__device__ float4 g_adst2[NMAX];
__device__ __align__(16) int g_count[NMAX + 4];   // edge-only counts
__device__ __align__(16) int g_rowptr[NMAX + 8];
__device__ __align__(16) int g_cursor[NMAX + 8];
__device__ int g_part[64];                 // per-tile sums for the scan
__device__ __align__(16) int g_dhist[NBINS];  // degree histogram
__device__ int g_dbase[NBINS];                // exclusive prefix (becomes cursor)
__device__ int g_perm[NMAX];                  // nodes sorted by degree
__device__ int g_colsrc[EMAX + NMAX];      // CSR column (src) indices, dst-sorted

__device__ __forceinline__ float warpsum(float v) {
  v += __shfl_xor_sync(0xffffffffu, v, 16);
  v += __shfl_xor_sync(0xffffffffu, v, 8);
  v += __shfl_xor_sync(0xffffffffu, v, 4);
  v += __shfl_xor_sync(0xffffffffu, v, 2);
  v += __shfl_xor_sync(0xffffffffu, v, 1);
  return v;
}

__device__ __forceinline__ float lrelu(float e) { return e > 0.f ? e : 0.2f * e; }

__device__ __forceinline__ uint32_t smem_u32(const void* p) {
  return (uint32_t)__cvta_generic_to_shared(p);
}

__device__ __forceinline__ void ldsm_x4(uint32_t& r0, uint32_t& r1, uint32_t& r2,
                                        uint32_t& r3, uint32_t addr) {
  asm volatile("ldmatrix.sync.aligned.m8n8.x4.shared.b16 {%0,%1,%2,%3}, [%4];"
               : "=r"(r0), "=r"(r1), "=r"(r2), "=r"(r3) : "r"(addr));
}

__device__ __forceinline__ void ldsm_x4_t(uint32_t& r0, uint32_t& r1, uint32_t& r2,
                                          uint32_t& r3, uint32_t addr) {
  asm volatile("ldmatrix.sync.aligned.m8n8.x4.trans.shared.b16 {%0,%1,%2,%3}, [%4];"
               : "=r"(r0), "=r"(r1), "=r"(r2), "=r"(r3) : "r"(addr));
}

__device__ __forceinline__ void mma16816(float& d0, float& d1, float& d2, float& d3,
                                         uint32_t a0, uint32_t a1, uint32_t a2,
                                         uint32_t a3, uint32_t b0, uint32_t b1) {
  asm volatile(
      "mma.sync.aligned.m16n8k16.row.col.f32.f16.f16.f32 "
      "{%0,%1,%2,%3}, {%4,%5,%6,%7}, {%8,%9}, {%0,%1,%2,%3};"
      : "+f"(d0), "+f"(d1), "+f"(d2), "+f"(d3)
      : "r"(a0), "r"(a1), "r"(a2), "r"(a3), "r"(b0), "r"(b1));
}

// ---------------- CSR build --------------------------------------------------
__global__ void zero_count_kernel(int N) {
  int gi = blockIdx.x * blockDim.x + threadIdx.x;
  int i = gi * 4;
  if (i < N + 4) *(int4*)&g_count[i] = make_int4(0, 0, 0, 0);
  if (gi < NBINS / 4) *(int4*)&g_dhist[gi * 4] = make_int4(0, 0, 0, 0);
}

// Fused: blocks [0, histBlocks) histogram edge dsts; remaining blocks run
// gemm1 (independent work, overlapped in one launch).
__global__ void hist_gemm1_kernel(const int* __restrict__ dstv, int E,
                                  const float* __restrict__ x,
                                  const float* __restrict__ W1,
                                  const float* __restrict__ att_s,
                                  const float* __restrict__ att_d, int N,
                                  int histBlocks) {
  if ((int)blockIdx.x < histBlocks) {
    int i = blockIdx.x * 256 + threadIdx.x;
    if (i < E) atomicAdd(&g_count[dstv[i]], 1);
    return;
  }
  // ---- gemm1: 256 threads = 2 column-groups of 128; 16 nodes per block ----
  __shared__ float sW[8 * 128];
  __shared__ float sAs[128], sAd[128];
  int tid = threadIdx.x;
  int tcol = tid & 127;  // output column
  int sub = tid >> 7;    // 0/1: which 8-node group
  if (tid < 128) {
    sAs[tid] = att_s[tid];
    sAd[tid] = att_d[tid];
  }
  for (int i = tid; i < 1024; i += 256) sW[i] = W1[i];
  __syncthreads();
  int head = tcol >> 5, lane = tid & 31;
  int base = ((int)blockIdx.x - histBlocks) * 16 + sub * 8;
  for (int m = 0; m < 8; ++m) {
    int n = base + m;
    if (n >= N) break;  // uniform across the 128-thread subgroup
    float acc = 0.f;
#pragma unroll
    for (int k = 0; k < 8; ++k) acc = fmaf(__ldg(&x[n * 8 + k]), sW[k * 128 + tcol], acc);
    g_h1h[(size_t)n * 128 + tcol] = __float2half(acc);
    float vs = warpsum(acc * sAs[tcol]);
    float vd = warpsum(acc * sAd[tcol]);
    if (lane == 0) {
      ((float*)&g_asrc1[n])[head] = vs;
      ((float*)&g_adst1[n])[head] = vd;
    }
  }
}

// Phase A: per-tile sums (int4 coalesced; +1 per valid node for self loops)
__global__ void scanA_kernel(int N) {
  __shared__ int red[1024];
  int b = blockIdx.x, t = threadIdx.x;
  int base = b * STILE + t * 4;
  int s = 0;
  if (base < N) {
    int4 v = *(const int4*)&g_count[base];  // zero-padded past N
    int vc = N - base; if (vc > 4) vc = 4;
    s = v.x + v.y + v.z + v.w + vc;         // + self loops
  }
  red[t] = s;
  __syncthreads();
  for (int off = 512; off > 0; off >>= 1) {
    if (t < off) red[t] += red[t + off];
    __syncthreads();
  }
  if (t == 0) g_part[b] = red[0];
}

// Phase C: in-tile scan + coalesced int4 writes + degree histogram.
__global__ void scanC_kernel(int N, int nb) {
  __shared__ int sPart[32];
  __shared__ int s[1024];
  __shared__ int hb[NBINS];
  int b = blockIdx.x, t = threadIdx.x;
  if (t < 32) {
    int v = (t < nb) ? g_part[t] : 0;
    int incl = v;
#pragma unroll
    for (int off = 1; off < 32; off <<= 1) {
      int u = __shfl_up_sync(0xffffffffu, incl, off);
      if (t >= off) incl += u;
    }
    sPart[t] = incl - v;  // exclusive prefix of tile sums
    if (t == 31 && b == 0) g_rowptr[N] = incl;  // total = E + N
  }
  hb[t] = 0;
  hb[t + 1024] = 0;
  int base = b * STILE + t * 4;
  int4 v = make_int4(0, 0, 0, 0);
  int vc = 0;
  if (base < N) {
    v = *(const int4*)&g_count[base];
    vc = N - base; if (vc > 4) vc = 4;
  }
  int mysum = v.x + v.y + v.z + v.w + vc;
  s[t] = mysum;
  __syncthreads();
  for (int off = 1; off < 1024; off <<= 1) {
    int u = (t >= off) ? s[t - off] : 0;
    __syncthreads();
    s[t] += u;
    __syncthreads();
  }
  int run = sPart[b] + s[t] - mysum;  // exclusive prefix for this thread
  int4 p;
  p.x = run;
  p.y = p.x + v.x + (vc > 0 ? 1 : 0);
  p.z = p.y + v.y + (vc > 1 ? 1 : 0);
  p.w = p.z + v.z + (vc > 2 ? 1 : 0);
  if (base < N) {
    *(int4*)&g_rowptr[base] = p;
    *(int4*)&g_cursor[base] = p;
    // degree histogram (self-loop included); sub-bin on node id to spread atomics
    int dv[4] = {v.x + 1, v.y + 1, v.z + 1, v.w + 1};
#pragma unroll
    for (int q = 0; q < 4; ++q) {
      if (q < vc) {
        int d = dv[q]; if (d > 255) d = 255;
        atomicAdd(&hb[(d << 3) | ((base + q) & 7)], 1);
      }
    }
  }
  __syncthreads();
  int h0 = hb[t], h1 = hb[t + 1024];
  if (h0) atomicAdd(&g_dhist[t], h0);
  if (h1) atomicAdd(&g_dhist[t + 1024], h1);
}

// Exclusive prefix over the 2048 degree bins (1 block).
__global__ void binprefix_kernel() {
  __shared__ int s[1024];
  int t = threadIdx.x;
  int a = g_dhist[2 * t], b = g_dhist[2 * t + 1];
  int sum = a + b;
  s[t] = sum;
  __syncthreads();
  for (int off = 1; off < 1024; off <<= 1) {
    int u = (t >= off) ? s[t - off] : 0;
    __syncthreads();
    s[t] += u;
    __syncthreads();
  }
  int excl = s[t] - sum;
  g_dbase[2 * t] = excl;
  g_dbase[2 * t + 1] = excl + a;
}

__global__ void scatter_kernel(const int* __restrict__ srcv,
                               const int* __restrict__ dstv, int E, int N) {
  int i = blockIdx.x * blockDim.x + threadIdx.x;
  if (i < E) {
    int p = atomicAdd(&g_cursor[dstv[i]], 1);
    g_colsrc[p] = srcv[i];
  } else if (i < E + N) {
    int n = i - E;  // self loop
    int p = atomicAdd(&g_cursor[n], 1);
    g_colsrc[p] = n;
    // degree-sorted permutation (counting-sort scatter)
    int d = g_rowptr[n + 1] - g_rowptr[n];
    if (d > 255) d = 255;
    int pp = atomicAdd(&g_dbase[(d << 3) | (n & 7)], 1);
    g_perm[pp] = n;
  }
}

// ---------------- layer-2 GEMM via HMMA tensor cores ------------------------
__global__ void gemm2_kernel(const float* __restrict__ W2,
                             const float* __restrict__ att_s,
                             const float* __restrict__ att_d, int N) {
  __shared__ __align__(16) __half sA[32 * 128];   // 8KB; reused as C (fp16)
  __shared__ __align__(16) __half sB[128 * 128];  // 32KB (W2 fp16, swizzled)
  __shared__ float4 sAs4[32], sAd4[32];
  int tid = threadIdx.x;  // 256
  int warp = tid >> 5, lane = tid & 31;
  int base = blockIdx.x * 32;

  if (tid < 32) {
    sAs4[tid] = ((const float4*)att_s)[tid];
    sAd4[tid] = ((const float4*)att_d)[tid];
  }

  for (int idx = tid; idx < 2048; idx += 256) {
    int k = idx >> 4, ch = idx & 15;
    const float4* src = (const float4*)(W2 + k * 128 + ch * 8);
    float4 w0 = src[0], w1 = src[1];
    __half2 p0 = __floats2half2_rn(w0.x, w0.y);
    __half2 p1 = __floats2half2_rn(w0.z, w0.w);
    __half2 p2 = __floats2half2_rn(w1.x, w1.y);
    __half2 p3 = __floats2half2_rn(w1.z, w1.w);
    uint4 v = make_uint4(*(unsigned*)&p0, *(unsigned*)&p1,
                         *(unsigned*)&p2, *(unsigned*)&p3);
    *(uint4*)(sB + k * 128 + ((ch ^ (k & 7)) << 3)) = v;
  }
  for (int idx = tid; idx < 512; idx += 256) {
    int r = idx >> 4, ch = idx & 15;
    int node = base + r;
    uint4 v = make_uint4(0u, 0u, 0u, 0u);
    if (node < N) v = *(const uint4*)(g_out1h + (size_t)node * 128 + ch * 8);
    *(uint4*)(sA + r * 128 + ((ch ^ (r & 7)) << 3)) = v;
  }
  __syncthreads();

  int wr = warp & 1;   // M: rows wr*16..+16
  int wc = warp >> 1;  // N: cols wc*32..+32
  int grp = lane >> 3;

  int a_row = wr * 16 + (lane & 7) + ((grp & 1) << 3);
  int b_krow_off = (lane & 7) + ((grp & 1) << 3);
  uint32_t sA_base = smem_u32(sA);
  uint32_t sB_base = smem_u32(sB);

  float d[4][4];
#pragma unroll
  for (int t = 0; t < 4; ++t)
#pragma unroll
    for (int j = 0; j < 4; ++j) d[t][j] = 0.f;

#pragma unroll
  for (int kk = 0; kk < 8; ++kk) {
    int a_ch = kk * 2 + (grp >> 1);
    uint32_t aaddr = sA_base + (uint32_t)(a_row * 256 + ((a_ch ^ (a_row & 7)) << 4));
    uint32_t a0, a1, a2, a3;
    ldsm_x4(a0, a1, a2, a3, aaddr);

    int k_row = kk * 16 + b_krow_off;
    int cb0 = wc * 4 + (grp >> 1);
    uint32_t baddr0 = sB_base + (uint32_t)(k_row * 256 + ((cb0 ^ (k_row & 7)) << 4));
    uint32_t baddr1 = sB_base + (uint32_t)(k_row * 256 + (((cb0 + 2) ^ (k_row & 7)) << 4));
    uint32_t b0, b1, b2, b3, b4, b5, b6, b7;
    ldsm_x4_t(b0, b1, b2, b3, baddr0);
    ldsm_x4_t(b4, b5, b6, b7, baddr1);

    mma16816(d[0][0], d[0][1], d[0][2], d[0][3], a0, a1, a2, a3, b0, b1);
    mma16816(d[1][0], d[1][1], d[1][2], d[1][3], a0, a1, a2, a3, b2, b3);
    mma16816(d[2][0], d[2][1], d[2][2], d[2][3], a0, a1, a2, a3, b4, b5);
    mma16816(d[3][0], d[3][1], d[3][2], d[3][3], a0, a1, a2, a3, b6, b7);
  }
  __syncthreads();

  {
    int crow = wr * 16 + (lane >> 2);
    int ccol0 = wc * 32 + (lane & 3) * 2;
#pragma unroll
    for (int t = 0; t < 4; ++t) {
      int c = ccol0 + t * 8;
      __half2 lo = __floats2half2_rn(d[t][0], d[t][1]);
      __half2 hi = __floats2half2_rn(d[t][2], d[t][3]);
      *(__half2*)(sA + crow * 128 + c) = lo;
      *(__half2*)(sA + (crow + 8) * 128 + c) = hi;
    }
  }
  __syncthreads();

  float4 as = sAs4[lane], ad = sAd4[lane];
  int head = lane >> 3;
#pragma unroll
  for (int m = 0; m < 4; ++m) {
    int r = warp * 4 + m;
    int n = base + r;
    uint2 u = *(uint2*)(sA + r * 128 + lane * 4);
    __half2 p0 = *(__half2*)&u.x;
    __half2 p1 = *(__half2*)&u.y;
    float2 f0 = __half22float2(p0);
    float2 f1 = __half22float2(p1);
    float ts = f0.x * as.x + f0.y * as.y + f1.x * as.z + f1.y * as.w;
    float td = f0.x * ad.x + f0.y * ad.y + f1.x * ad.z + f1.y * ad.w;
    ts += __shfl_xor_sync(0xffffffffu, ts, 1);
    ts += __shfl_xor_sync(0xffffffffu, ts, 2);
    ts += __shfl_xor_sync(0xffffffffu, ts, 4);
    td += __shfl_xor_sync(0xffffffffu, td, 1);
    td += __shfl_xor_sync(0xffffffffu, td, 2);
    td += __shfl_xor_sync(0xffffffffu, td, 4);
    if (n < N) {
      *(uint2*)(g_h2h + (size_t)n * 128 + lane * 4) = u;
      if ((lane & 7) == 0) {
        ((float*)&g_asrc2[n])[head] = ts;
        ((float*)&g_adst2[n])[head] = td;
      }
    }
  }
}

// ---------------- GAT aggregation: warp per dst node, single pass -----------
// Nodes processed in degree-sorted order (g_perm) -> warps in a block have
// near-equal work -> no block-straggler waste. 8-wide gather batches.
__device__ __forceinline__ void acc_h4(const __half* __restrict__ hh, int s,
                                       int lane, float al,
                                       float& ax, float& ay, float& az, float& aw) {
  uint2 u = *(const uint2*)(hh + (size_t)s * 128 + lane * 4);
  __half2 p0 = *(__half2*)&u.x;
  __half2 p1 = *(__half2*)&u.y;
  float2 f0 = __half22float2(p0);
  float2 f1 = __half22float2(p1);
  ax = fmaf(f0.x, al, ax);
  ay = fmaf(f0.y, al, ay);
  az = fmaf(f1.x, al, az);
  aw = fmaf(f1.y, al, aw);
}

__global__ void __launch_bounds__(256)
gat_aggregate_kernel(float* __restrict__ dout,
                     const float* __restrict__ bias,
                     const float* __restrict__ wlin,
                     const float* __restrict__ blin,
                     int N, int mode) {
  int gw0 = (blockIdx.x * blockDim.x + threadIdx.x) >> 5;
  int lane = threadIdx.x & 31;
  if (gw0 >= N) return;
  int gw = g_perm[gw0];  // degree-sorted schedule

  const __half* hh    = (mode == 0) ? g_h1h : g_h2h;
  const float*  asrcf = (const float*)((mode == 0) ? g_asrc1 : g_asrc2);
  const float*  adstf = (const float*)((mode == 0) ? g_adst1 : g_adst2);

  int rs = g_rowptr[gw], re = g_rowptr[gw + 1];
  int head = lane >> 3;  // lane owns channels [4*lane, 4*lane+4)
  float adh = __ldg(&adstf[gw * 4 + head]);

  float ax = 0.f, ay = 0.f, az = 0.f, aw = 0.f, den = 0.f;

  for (int c = rs; c < re; c += 32) {
    int cnt = re - c; if (cnt > 32) cnt = 32;
    int idx = c + lane;
    int sv = g_colsrc[idx < re ? idx : re - 1];  // coalesced prefetch
    int j = 0;
    for (; j + 8 <= cnt; j += 8) {
      int s[8];
#pragma unroll
      for (int u = 0; u < 8; ++u) s[u] = __shfl_sync(0xffffffffu, sv, j + u);
      float av[8];
#pragma unroll
      for (int u = 0; u < 8; ++u) av[u] = __ldg(&asrcf[s[u] * 4 + head]);
      float al[8];
#pragma unroll
      for (int u = 0; u < 8; ++u) al[u] = __expf(lrelu(av[u] + adh));
#pragma unroll
      for (int u = 0; u < 8; ++u) {
        acc_h4(hh, s[u], lane, al[u], ax, ay, az, aw);
        den += al[u];
      }
    }
    for (; j < cnt; ++j) {
      int s0 = __shfl_sync(0xffffffffu, sv, j);
      float al = __expf(lrelu(__ldg(&asrcf[s0 * 4 + head]) + adh));
      acc_h4(hh, s0, lane, al, ax, ay, az, aw);
      den += al;
    }
  }
  float rd = 1.0f / den;  // den identical across each head's 8 lanes
  ax *= rd; ay *= rd; az *= rd; aw *= rd;

  if (mode == 0) {
    float4 b = ((const float4*)bias)[lane];
    __half2 lo = __floats2half2_rn(fmaxf(ax + b.x, 0.f), fmaxf(ay + b.y, 0.f));
    __half2 hi = __floats2half2_rn(fmaxf(az + b.z, 0.f), fmaxf(aw + b.w, 0.f));
    uint2 packed;
    packed.x = *(unsigned*)&lo;
    packed.y = *(unsigned*)&hi;
    *(uint2*)(g_out1h + (size_t)gw * 128 + lane * 4) = packed;  // device symbol
  } else {
    ax += __shfl_xor_sync(0xffffffffu, ax, 8);
    ax += __shfl_xor_sync(0xffffffffu, ax, 16);
    ay += __shfl_xor_sync(0xffffffffu, ay, 8);
    ay += __shfl_xor_sync(0xffffffffu, ay, 16);
    az += __shfl_xor_sync(0xffffffffu, az, 8);
    az += __shfl_xor_sync(0xffffffffu, az, 16);
    aw += __shfl_xor_sync(0xffffffffu, aw, 8);
    aw += __shfl_xor_sync(0xffffffffu, aw, 16);
    int c0 = (lane & 7) * 4;
    float v0 = fmaxf(ax * 0.25f + bias[c0 + 0], 0.f);
    float v1 = fmaxf(ay * 0.25f + bias[c0 + 1], 0.f);
    float v2 = fmaxf(az * 0.25f + bias[c0 + 2], 0.f);
    float v3 = fmaxf(aw * 0.25f + bias[c0 + 3], 0.f);
    float p = v0 * wlin[c0] + v1 * wlin[c0 + 1] + v2 * wlin[c0 + 2] + v3 * wlin[c0 + 3];
    p += __shfl_xor_sync(0xffffffffu, p, 1);
    p += __shfl_xor_sync(0xffffffffu, p, 2);
    p += __shfl_xor_sync(0xffffffffu, p, 4);
    if (lane == 0) dout[gw] = p + blin[0];
  }
}

// ---------------- launch -----------------------------------------------------
extern "C" void kernel_launch(void* const* d_in, const int* in_sizes, int n_in,
                              void* d_out, int out_size) {
  const float* x    = (const float*)d_in[0];
  const int*   ei   = (const int*)d_in[1];
  const float* W1   = (const float*)d_in[2];
  const float* as1  = (const float*)d_in[3];
  const float* ad1  = (const float*)d_in[4];
  const float* b1   = (const float*)d_in[5];
  const float* W2   = (const float*)d_in[6];
  const float* as2  = (const float*)d_in[7];
  const float* ad2  = (const float*)d_in[8];
  const float* b2   = (const float*)d_in[9];
  const float* wlin = (const float*)d_in[10];
  const float* blin = (const float*)d_in[11];

  int N = in_sizes[0] / 8;
  int E = in_sizes[1] / 2;
  const int* srcv = ei;
  const int* dstv = ei + E;
  int ntiles = (N + STILE - 1) / STILE;
  int histBlocks = (E + 255) / 256;
  int gemm1Blocks = (N + 15) / 16;

  // CSR build, with gemm1 overlapped into the histogram launch
  zero_count_kernel<<<(N / 4 + 256) / 256, 256>>>(N);
  hist_gemm1_kernel<<<histBlocks + gemm1Blocks, 256>>>(dstv, E, x, W1, as1, ad1,
                                                       N, histBlocks);
  scanA_kernel<<<ntiles, 1024>>>(N);
  scanC_kernel<<<ntiles, 1024>>>(N, ntiles);
  binprefix_kernel<<<1, 1024>>>();
  scatter_kernel<<<(E + N + 255) / 256, 256>>>(srcv, dstv, E, N);

  // layer 1 aggregate (writes g_out1h internally)
  gat_aggregate_kernel<<<(N + 7) / 8, 256>>>((float*)d_out, b1, nullptr, nullptr, N, 0);

  // layer 2: tensor-core GEMM + fused epilogues
  gemm2_kernel<<<(N + 31) / 32, 256>>>(W2, as2, ad2, N);
  gat_aggregate_kernel<<<(N + 7) / 8, 256>>>((float*)d_out, b2, wlin, blin, N, 1);
}

// round 14
// speedup vs baseline: 1.0373x; 1.0373x over previous
#include <cuda_runtime.h>
#include <cuda_fp16.h>
#include <cstdint>

// Problem-shape upper bounds (N=100000, E=1600000 for this dataset).
#define NMAX 100000
#define EMAX 1600000
#define STILE 4096  // scan tile: 1024 threads x int4

// ---------------- scratch (static device globals) ---------------------------
__device__ __align__(16) __half g_h1h[(size_t)NMAX * 128];   // layer1 features (fp16)
__device__ __align__(16) __half g_h2h[(size_t)NMAX * 128];   // layer2 features (fp16)
__device__ __align__(16) __half g_out1h[(size_t)NMAX * 128]; // relu(gat1+b1) (fp16)
__device__ float4 g_asrc1[NMAX];
__device__ float4 g_adst1[NMAX];
__device__ float4 g_asrc2[NMAX];
__device__ float4 g_adst2[NMAX];
__device__ __align__(16) int g_count[NMAX + 4];   // edge-only counts
__device__ __align__(16) int g_rowptr[NMAX + 8];
__device__ __align__(16) int g_cursor[NMAX + 8];
__device__ int g_part[64];                 // per-tile sums for the scan
__device__ int g_aggctr[2];                // work-stealing counters (per layer)
__device__ int g_colsrc[EMAX + NMAX];      // CSR column (src) indices, dst-sorted

__device__ __forceinline__ float warpsum(float v) {
  v += __shfl_xor_sync(0xffffffffu, v, 16);
  v += __shfl_xor_sync(0xffffffffu, v, 8);
  v += __shfl_xor_sync(0xffffffffu, v, 4);
  v += __shfl_xor_sync(0xffffffffu, v, 2);
  v += __shfl_xor_sync(0xffffffffu, v, 1);
  return v;
}

__device__ __forceinline__ float lrelu(float e) { return e > 0.f ? e : 0.2f * e; }

__device__ __forceinline__ uint32_t smem_u32(const void* p) {
  return (uint32_t)__cvta_generic_to_shared(p);
}

__device__ __forceinline__ void ldsm_x4(uint32_t& r0, uint32_t& r1, uint32_t& r2,
                                        uint32_t& r3, uint32_t addr) {
  asm volatile("ldmatrix.sync.aligned.m8n8.x4.shared.b16 {%0,%1,%2,%3}, [%4];"
               : "=r"(r0), "=r"(r1), "=r"(r2), "=r"(r3) : "r"(addr));
}

__device__ __forceinline__ void ldsm_x4_t(uint32_t& r0, uint32_t& r1, uint32_t& r2,
                                          uint32_t& r3, uint32_t addr) {
  asm volatile("ldmatrix.sync.aligned.m8n8.x4.trans.shared.b16 {%0,%1,%2,%3}, [%4];"
               : "=r"(r0), "=r"(r1), "=r"(r2), "=r"(r3) : "r"(addr));
}

__device__ __forceinline__ void mma16816(float& d0, float& d1, float& d2, float& d3,
                                         uint32_t a0, uint32_t a1, uint32_t a2,
                                         uint32_t a3, uint32_t b0, uint32_t b1) {
  asm volatile(
      "mma.sync.aligned.m16n8k16.row.col.f32.f16.f16.f32 "
      "{%0,%1,%2,%3}, {%4,%5,%6,%7}, {%8,%9}, {%0,%1,%2,%3};"
      : "+f"(d0), "+f"(d1), "+f"(d2), "+f"(d3)
      : "r"(a0), "r"(a1), "r"(a2), "r"(a3), "r"(b0), "r"(b1));
}

// ---------------- CSR build --------------------------------------------------
__global__ void zero_count_kernel(int N) {
  int gi = blockIdx.x * blockDim.x + threadIdx.x;
  int i = gi * 4;
  if (i < N + 4) *(int4*)&g_count[i] = make_int4(0, 0, 0, 0);
  if (gi == 0) { g_aggctr[0] = 0; g_aggctr[1] = 0; }
}

// Fused: blocks [0, histBlocks) histogram edge dsts; remaining blocks run
// gemm1 (independent work, overlapped in one launch).
__global__ void hist_gemm1_kernel(const int* __restrict__ dstv, int E,
                                  const float* __restrict__ x,
                                  const float* __restrict__ W1,
                                  const float* __restrict__ att_s,
                                  const float* __restrict__ att_d, int N,
                                  int histBlocks) {
  if ((int)blockIdx.x < histBlocks) {
    int i = blockIdx.x * 256 + threadIdx.x;
    if (i < E) atomicAdd(&g_count[dstv[i]], 1);
    return;
  }
  // ---- gemm1: 256 threads = 2 column-groups of 128; 16 nodes per block ----
  __shared__ float sW[8 * 128];
  __shared__ float sAs[128], sAd[128];
  int tid = threadIdx.x;
  int tcol = tid & 127;  // output column
  int sub = tid >> 7;    // 0/1: which 8-node group
  if (tid < 128) {
    sAs[tid] = att_s[tid];
    sAd[tid] = att_d[tid];
  }
  for (int i = tid; i < 1024; i += 256) sW[i] = W1[i];
  __syncthreads();
  int head = tcol >> 5, lane = tid & 31;
  int base = ((int)blockIdx.x - histBlocks) * 16 + sub * 8;
  for (int m = 0; m < 8; ++m) {
    int n = base + m;
    if (n >= N) break;  // uniform across the 128-thread subgroup
    float acc = 0.f;
#pragma unroll
    for (int k = 0; k < 8; ++k) acc = fmaf(__ldg(&x[n * 8 + k]), sW[k * 128 + tcol], acc);
    g_h1h[(size_t)n * 128 + tcol] = __float2half(acc);
    float vs = warpsum(acc * sAs[tcol]);
    float vd = warpsum(acc * sAd[tcol]);
    if (lane == 0) {
      ((float*)&g_asrc1[n])[head] = vs;
      ((float*)&g_adst1[n])[head] = vd;
    }
  }
}

// Phase A: per-tile sums (int4 coalesced; +1 per valid node for self loops)
__global__ void scanA_kernel(int N) {
  __shared__ int red[1024];
  int b = blockIdx.x, t = threadIdx.x;
  int base = b * STILE + t * 4;
  int s = 0;
  if (base < N) {
    int4 v = *(const int4*)&g_count[base];  // zero-padded past N
    int vc = N - base; if (vc > 4) vc = 4;
    s = v.x + v.y + v.z + v.w + vc;         // + self loops
  }
  red[t] = s;
  __syncthreads();
  for (int off = 512; off > 0; off >>= 1) {
    if (t < off) red[t] += red[t + off];
    __syncthreads();
  }
  if (t == 0) g_part[b] = red[0];
}

// Phase C: in-tile scan + coalesced int4 writes. The (tiny, nb<=32) tile-sum
// prefix scan is redone locally per block -> no separate scanB launch.
__global__ void scanC_kernel(int N, int nb) {
  __shared__ int sPart[32];
  __shared__ int s[1024];
  int b = blockIdx.x, t = threadIdx.x;
  if (t < 32) {
    int v = (t < nb) ? g_part[t] : 0;
    int incl = v;
#pragma unroll
    for (int off = 1; off < 32; off <<= 1) {
      int u = __shfl_up_sync(0xffffffffu, incl, off);
      if (t >= off) incl += u;
    }
    sPart[t] = incl - v;  // exclusive prefix of tile sums
    if (t == 31 && b == 0) g_rowptr[N] = incl;  // total = E + N
  }
  int base = b * STILE + t * 4;
  int4 v = make_int4(0, 0, 0, 0);
  int vc = 0;
  if (base < N) {
    v = *(const int4*)&g_count[base];
    vc = N - base; if (vc > 4) vc = 4;
  }
  int mysum = v.x + v.y + v.z + v.w + vc;
  s[t] = mysum;
  __syncthreads();
  for (int off = 1; off < 1024; off <<= 1) {
    int u = (t >= off) ? s[t - off] : 0;
    __syncthreads();
    s[t] += u;
    __syncthreads();
  }
  int run = sPart[b] + s[t] - mysum;  // exclusive prefix for this thread
  int4 p;
  p.x = run;
  p.y = p.x + v.x + (vc > 0 ? 1 : 0);
  p.z = p.y + v.y + (vc > 1 ? 1 : 0);
  p.w = p.z + v.z + (vc > 2 ? 1 : 0);
  if (base < N) {
    *(int4*)&g_rowptr[base] = p;
    *(int4*)&g_cursor[base] = p;
  }
}

__global__ void scatter_kernel(const int* __restrict__ srcv,
                               const int* __restrict__ dstv, int E, int N) {
  int i = blockIdx.x * blockDim.x + threadIdx.x;
  if (i < E) {
    int p = atomicAdd(&g_cursor[dstv[i]], 1);
    g_colsrc[p] = srcv[i];
  } else if (i < E + N) {
    int n = i - E;  // self loop
    int p = atomicAdd(&g_cursor[n], 1);
    g_colsrc[p] = n;
  }
}

// ---------------- layer-2 GEMM via HMMA tensor cores ------------------------
__global__ void gemm2_kernel(const float* __restrict__ W2,
                             const float* __restrict__ att_s,
                             const float* __restrict__ att_d, int N) {
  __shared__ __align__(16) __half sA[32 * 128];   // 8KB; reused as C (fp16)
  __shared__ __align__(16) __half sB[128 * 128];  // 32KB (W2 fp16, swizzled)
  __shared__ float4 sAs4[32], sAd4[32];
  int tid = threadIdx.x;  // 256
  int warp = tid >> 5, lane = tid & 31;
  int base = blockIdx.x * 32;

  if (tid < 32) {
    sAs4[tid] = ((const float4*)att_s)[tid];
    sAd4[tid] = ((const float4*)att_d)[tid];
  }

  for (int idx = tid; idx < 2048; idx += 256) {
    int k = idx >> 4, ch = idx & 15;
    const float4* src = (const float4*)(W2 + k * 128 + ch * 8);
    float4 w0 = src[0], w1 = src[1];
    __half2 p0 = __floats2half2_rn(w0.x, w0.y);
    __half2 p1 = __floats2half2_rn(w0.z, w0.w);
    __half2 p2 = __floats2half2_rn(w1.x, w1.y);
    __half2 p3 = __floats2half2_rn(w1.z, w1.w);
    uint4 v = make_uint4(*(unsigned*)&p0, *(unsigned*)&p1,
                         *(unsigned*)&p2, *(unsigned*)&p3);
    *(uint4*)(sB + k * 128 + ((ch ^ (k & 7)) << 3)) = v;
  }
  for (int idx = tid; idx < 512; idx += 256) {
    int r = idx >> 4, ch = idx & 15;
    int node = base + r;
    uint4 v = make_uint4(0u, 0u, 0u, 0u);
    if (node < N) v = *(const uint4*)(g_out1h + (size_t)node * 128 + ch * 8);
    *(uint4*)(sA + r * 128 + ((ch ^ (r & 7)) << 3)) = v;
  }
  __syncthreads();

  int wr = warp & 1;   // M: rows wr*16..+16
  int wc = warp >> 1;  // N: cols wc*32..+32
  int grp = lane >> 3;

  int a_row = wr * 16 + (lane & 7) + ((grp & 1) << 3);
  int b_krow_off = (lane & 7) + ((grp & 1) << 3);
  uint32_t sA_base = smem_u32(sA);
  uint32_t sB_base = smem_u32(sB);

  float d[4][4];
#pragma unroll
  for (int t = 0; t < 4; ++t)
#pragma unroll
    for (int j = 0; j < 4; ++j) d[t][j] = 0.f;

#pragma unroll
  for (int kk = 0; kk < 8; ++kk) {
    int a_ch = kk * 2 + (grp >> 1);
    uint32_t aaddr = sA_base + (uint32_t)(a_row * 256 + ((a_ch ^ (a_row & 7)) << 4));
    uint32_t a0, a1, a2, a3;
    ldsm_x4(a0, a1, a2, a3, aaddr);

    int k_row = kk * 16 + b_krow_off;
    int cb0 = wc * 4 + (grp >> 1);
    uint32_t baddr0 = sB_base + (uint32_t)(k_row * 256 + ((cb0 ^ (k_row & 7)) << 4));
    uint32_t baddr1 = sB_base + (uint32_t)(k_row * 256 + (((cb0 + 2) ^ (k_row & 7)) << 4));
    uint32_t b0, b1, b2, b3, b4, b5, b6, b7;
    ldsm_x4_t(b0, b1, b2, b3, baddr0);
    ldsm_x4_t(b4, b5, b6, b7, baddr1);

    mma16816(d[0][0], d[0][1], d[0][2], d[0][3], a0, a1, a2, a3, b0, b1);
    mma16816(d[1][0], d[1][1], d[1][2], d[1][3], a0, a1, a2, a3, b2, b3);
    mma16816(d[2][0], d[2][1], d[2][2], d[2][3], a0, a1, a2, a3, b4, b5);
    mma16816(d[3][0], d[3][1], d[3][2], d[3][3], a0, a1, a2, a3, b6, b7);
  }
  __syncthreads();

  {
    int crow = wr * 16 + (lane >> 2);
    int ccol0 = wc * 32 + (lane & 3) * 2;
#pragma unroll
    for (int t = 0; t < 4; ++t) {
      int c = ccol0 + t * 8;
      __half2 lo = __floats2half2_rn(d[t][0], d[t][1]);
      __half2 hi = __floats2half2_rn(d[t][2], d[t][3]);
      *(__half2*)(sA + crow * 128 + c) = lo;
      *(__half2*)(sA + (crow + 8) * 128 + c) = hi;
    }
  }
  __syncthreads();

  float4 as = sAs4[lane], ad = sAd4[lane];
  int head = lane >> 3;
#pragma unroll
  for (int m = 0; m < 4; ++m) {
    int r = warp * 4 + m;
    int n = base + r;
    uint2 u = *(uint2*)(sA + r * 128 + lane * 4);
    __half2 p0 = *(__half2*)&u.x;
    __half2 p1 = *(__half2*)&u.y;
    float2 f0 = __half22float2(p0);
    float2 f1 = __half22float2(p1);
    float ts = f0.x * as.x + f0.y * as.y + f1.x * as.z + f1.y * as.w;
    float td = f0.x * ad.x + f0.y * ad.y + f1.x * ad.z + f1.y * ad.w;
    ts += __shfl_xor_sync(0xffffffffu, ts, 1);
    ts += __shfl_xor_sync(0xffffffffu, ts, 2);
    ts += __shfl_xor_sync(0xffffffffu, ts, 4);
    td += __shfl_xor_sync(0xffffffffu, td, 1);
    td += __shfl_xor_sync(0xffffffffu, td, 2);
    td += __shfl_xor_sync(0xffffffffu, td, 4);
    if (n < N) {
      *(uint2*)(g_h2h + (size_t)n * 128 + lane * 4) = u;
      if ((lane & 7) == 0) {
        ((float*)&g_asrc2[n])[head] = ts;
        ((float*)&g_adst2[n])[head] = td;
      }
    }
  }
}

// ---------------- GAT aggregation: persistent warps + work stealing ---------
// Warps grab batches of 8 CONSECUTIVE nodes from a global counter: node order
// (and thus memory locality) is preserved, but no warp idles behind a block
// straggler. 8-wide gather batches inside (proven R8 config).
__device__ __forceinline__ void acc_h4(const __half* __restrict__ hh, int s,
                                       int lane, float al,
                                       float& ax, float& ay, float& az, float& aw) {
  uint2 u = *(const uint2*)(hh + (size_t)s * 128 + lane * 4);
  __half2 p0 = *(__half2*)&u.x;
  __half2 p1 = *(__half2*)&u.y;
  float2 f0 = __half22float2(p0);
  float2 f1 = __half22float2(p1);
  ax = fmaf(f0.x, al, ax);
  ay = fmaf(f0.y, al, ay);
  az = fmaf(f1.x, al, az);
  aw = fmaf(f1.y, al, aw);
}

#define AGG_BATCH 8

__global__ void __launch_bounds__(256)
gat_aggregate_kernel(float* __restrict__ dout,
                     const float* __restrict__ bias,
                     const float* __restrict__ wlin,
                     const float* __restrict__ blin,
                     int N, int mode) {
  int lane = threadIdx.x & 31;

  const __half* hh    = (mode == 0) ? g_h1h : g_h2h;
  const float*  asrcf = (const float*)((mode == 0) ? g_asrc1 : g_asrc2);
  const float*  adstf = (const float*)((mode == 0) ? g_adst1 : g_adst2);
  int head = lane >> 3;  // lane owns channels [4*lane, 4*lane+4)

  for (;;) {
    int base;
    if (lane == 0) base = atomicAdd(&g_aggctr[mode], AGG_BATCH);
    base = __shfl_sync(0xffffffffu, base, 0);
    if (base >= N) return;
    int bend = base + AGG_BATCH; if (bend > N) bend = N;

    for (int gw = base; gw < bend; ++gw) {
      int rs = g_rowptr[gw], re = g_rowptr[gw + 1];
      float adh = __ldg(&adstf[gw * 4 + head]);

      float ax = 0.f, ay = 0.f, az = 0.f, aw = 0.f, den = 0.f;

      for (int c = rs; c < re; c += 32) {
        int cnt = re - c; if (cnt > 32) cnt = 32;
        int idx = c + lane;
        int sv = g_colsrc[idx < re ? idx : re - 1];  // coalesced prefetch
        int j = 0;
        for (; j + 8 <= cnt; j += 8) {
          int s[8];
#pragma unroll
          for (int u = 0; u < 8; ++u) s[u] = __shfl_sync(0xffffffffu, sv, j + u);
          float av[8];
#pragma unroll
          for (int u = 0; u < 8; ++u) av[u] = __ldg(&asrcf[s[u] * 4 + head]);
          float al[8];
#pragma unroll
          for (int u = 0; u < 8; ++u) al[u] = __expf(lrelu(av[u] + adh));
#pragma unroll
          for (int u = 0; u < 8; ++u) {
            acc_h4(hh, s[u], lane, al[u], ax, ay, az, aw);
            den += al[u];
          }
        }
        for (; j < cnt; ++j) {
          int s0 = __shfl_sync(0xffffffffu, sv, j);
          float al = __expf(lrelu(__ldg(&asrcf[s0 * 4 + head]) + adh));
          acc_h4(hh, s0, lane, al, ax, ay, az, aw);
          den += al;
        }
      }
      float rd = 1.0f / den;  // den identical across each head's 8 lanes
      ax *= rd; ay *= rd; az *= rd; aw *= rd;

      if (mode == 0) {
        float4 b = ((const float4*)bias)[lane];
        __half2 lo = __floats2half2_rn(fmaxf(ax + b.x, 0.f), fmaxf(ay + b.y, 0.f));
        __half2 hi = __floats2half2_rn(fmaxf(az + b.z, 0.f), fmaxf(aw + b.w, 0.f));
        uint2 packed;
        packed.x = *(unsigned*)&lo;
        packed.y = *(unsigned*)&hi;
        *(uint2*)(g_out1h + (size_t)gw * 128 + lane * 4) = packed;  // device symbol
      } else {
        ax += __shfl_xor_sync(0xffffffffu, ax, 8);
        ax += __shfl_xor_sync(0xffffffffu, ax, 16);
        ay += __shfl_xor_sync(0xffffffffu, ay, 8);
        ay += __shfl_xor_sync(0xffffffffu, ay, 16);
        az += __shfl_xor_sync(0xffffffffu, az, 8);
        az += __shfl_xor_sync(0xffffffffu, az, 16);
        aw += __shfl_xor_sync(0xffffffffu, aw, 8);
        aw += __shfl_xor_sync(0xffffffffu, aw, 16);
        int c0 = (lane & 7) * 4;
        float v0 = fmaxf(ax * 0.25f + bias[c0 + 0], 0.f);
        float v1 = fmaxf(ay * 0.25f + bias[c0 + 1], 0.f);
        float v2 = fmaxf(az * 0.25f + bias[c0 + 2], 0.f);
        float v3 = fmaxf(aw * 0.25f + bias[c0 + 3], 0.f);
        float p = v0 * wlin[c0] + v1 * wlin[c0 + 1] + v2 * wlin[c0 + 2] + v3 * wlin[c0 + 3];
        p += __shfl_xor_sync(0xffffffffu, p, 1);
        p += __shfl_xor_sync(0xffffffffu, p, 2);
        p += __shfl_xor_sync(0xffffffffu, p, 4);
        if (lane == 0) dout[gw] = p + blin[0];
      }
    }
  }
}

// ---------------- launch -----------------------------------------------------
extern "C" void kernel_launch(void* const* d_in, const int* in_sizes, int n_in,
                              void* d_out, int out_size) {
  const float* x    = (const float*)d_in[0];
  const int*   ei   = (const int*)d_in[1];
  const float* W1   = (const float*)d_in[2];
  const float* as1  = (const float*)d_in[3];
  const float* ad1  = (const float*)d_in[4];
  const float* b1   = (const float*)d_in[5];
  const float* W2   = (const float*)d_in[6];
  const float* as2  = (const float*)d_in[7];
  const float* ad2  = (const float*)d_in[8];
  const float* b2   = (const float*)d_in[9];
  const float* wlin = (const float*)d_in[10];
  const float* blin = (const float*)d_in[11];

  int N = in_sizes[0] / 8;
  int E = in_sizes[1] / 2;
  const int* srcv = ei;
  const int* dstv = ei + E;
  int ntiles = (N + STILE - 1) / STILE;
  int histBlocks = (E + 255) / 256;
  int gemm1Blocks = (N + 15) / 16;
  int aggBlocks = 148 * 8;  // persistent: ~1 residency wave of 8-warp blocks

  // CSR build, with gemm1 overlapped into the histogram launch
  zero_count_kernel<<<(N / 4 + 256) / 256, 256>>>(N);
  hist_gemm1_kernel<<<histBlocks + gemm1Blocks, 256>>>(dstv, E, x, W1, as1, ad1,
                                                       N, histBlocks);
  scanA_kernel<<<ntiles, 1024>>>(N);
  scanC_kernel<<<ntiles, 1024>>>(N, ntiles);  // scanB folded in
  scatter_kernel<<<(E + N + 255) / 256, 256>>>(srcv, dstv, E, N);

  // layer 1 aggregate (writes g_out1h internally)
  gat_aggregate_kernel<<<aggBlocks, 256>>>((float*)d_out, b1, nullptr, nullptr, N, 0);

  // layer 2: tensor-core GEMM + fused epilogues
  gemm2_kernel<<<(N + 31) / 32, 256>>>(W2, as2, ad2, N);
  gat_aggregate_kernel<<<aggBlocks, 256>>>((float*)d_out, b2, wlin, blin, N, 1);
}

// round 15
// speedup vs baseline: 1.0919x; 1.0526x over previous
#include <cuda_runtime.h>
#include <cuda_fp16.h>
#include <cstdint>

// Problem-shape upper bounds (N=100000, E=1600000 for this dataset).
#define NMAX 100000
#define EMAX 1600000
#define STILE 4096  // scan tile: 1024 threads x int4

// ---------------- scratch (static device globals) ---------------------------
__device__ __align__(16) __half g_h1h[(size_t)NMAX * 128];   // layer1 features (fp16)
__device__ __align__(16) __half g_h2h[(size_t)NMAX * 128];   // layer2 features (fp16)
__device__ __align__(16) __half g_out1h[(size_t)NMAX * 128]; // relu(gat1+b1) (fp16)
__device__ __align__(16) __half g_W2h[128 * 128];            // W2 pre-converted fp16
__device__ float4 g_asrc1[NMAX];
__device__ float4 g_adst1[NMAX];
__device__ float4 g_asrc2[NMAX];
__device__ float4 g_adst2[NMAX];
__device__ __align__(16) int g_count[NMAX + 4];   // edge-only counts
__device__ __align__(16) int g_rowptr[NMAX + 8];
__device__ __align__(16) int g_cursor[NMAX + 8];
__device__ int g_part[64];                 // per-tile sums for the scan
__device__ int g_colsrc[EMAX + NMAX];      // CSR column (src) indices, dst-sorted

__device__ __forceinline__ float warpsum(float v) {
  v += __shfl_xor_sync(0xffffffffu, v, 16);
  v += __shfl_xor_sync(0xffffffffu, v, 8);
  v += __shfl_xor_sync(0xffffffffu, v, 4);
  v += __shfl_xor_sync(0xffffffffu, v, 2);
  v += __shfl_xor_sync(0xffffffffu, v, 1);
  return v;
}

__device__ __forceinline__ float lrelu(float e) { return e > 0.f ? e : 0.2f * e; }

__device__ __forceinline__ uint32_t smem_u32(const void* p) {
  return (uint32_t)__cvta_generic_to_shared(p);
}

__device__ __forceinline__ void ldsm_x4(uint32_t& r0, uint32_t& r1, uint32_t& r2,
                                        uint32_t& r3, uint32_t addr) {
  asm volatile("ldmatrix.sync.aligned.m8n8.x4.shared.b16 {%0,%1,%2,%3}, [%4];"
               : "=r"(r0), "=r"(r1), "=r"(r2), "=r"(r3) : "r"(addr));
}

__device__ __forceinline__ void ldsm_x4_t(uint32_t& r0, uint32_t& r1, uint32_t& r2,
                                          uint32_t& r3, uint32_t addr) {
  asm volatile("ldmatrix.sync.aligned.m8n8.x4.trans.shared.b16 {%0,%1,%2,%3}, [%4];"
               : "=r"(r0), "=r"(r1), "=r"(r2), "=r"(r3) : "r"(addr));
}

__device__ __forceinline__ void mma16816(float& d0, float& d1, float& d2, float& d3,
                                         uint32_t a0, uint32_t a1, uint32_t a2,
                                         uint32_t a3, uint32_t b0, uint32_t b1) {
  asm volatile(
      "mma.sync.aligned.m16n8k16.row.col.f32.f16.f16.f32 "
      "{%0,%1,%2,%3}, {%4,%5,%6,%7}, {%8,%9}, {%0,%1,%2,%3};"
      : "+f"(d0), "+f"(d1), "+f"(d2), "+f"(d3)
      : "r"(a0), "r"(a1), "r"(a2), "r"(a3), "r"(b0), "r"(b1));
}

// ---------------- CSR build + W2 fp16 pre-conversion -------------------------
__global__ void zero_count_kernel(const float* __restrict__ W2, int N) {
  int gi = blockIdx.x * blockDim.x + threadIdx.x;
  int i = gi * 4;
  if (i < N + 4) *(int4*)&g_count[i] = make_int4(0, 0, 0, 0);
  if (gi < 4096) {  // convert W2 (16384 floats) to fp16, 4 per thread
    float4 w = *(const float4*)(W2 + gi * 4);
    __half2 lo = __floats2half2_rn(w.x, w.y);
    __half2 hi = __floats2half2_rn(w.z, w.w);
    uint2 p;
    p.x = *(unsigned*)&lo;
    p.y = *(unsigned*)&hi;
    *(uint2*)(g_W2h + gi * 4) = p;
  }
}

// Fused: blocks [0, histBlocks) histogram edge dsts; remaining blocks run
// gemm1 (independent work, overlapped in one launch).
__global__ void hist_gemm1_kernel(const int* __restrict__ dstv, int E,
                                  const float* __restrict__ x,
                                  const float* __restrict__ W1,
                                  const float* __restrict__ att_s,
                                  const float* __restrict__ att_d, int N,
                                  int histBlocks) {
  if ((int)blockIdx.x < histBlocks) {
    int i = blockIdx.x * 256 + threadIdx.x;
    if (i < E) atomicAdd(&g_count[dstv[i]], 1);
    return;
  }
  // ---- gemm1: 256 threads = 2 column-groups of 128; 16 nodes per block ----
  __shared__ float sW[8 * 128];
  __shared__ float sAs[128], sAd[128];
  int tid = threadIdx.x;
  int tcol = tid & 127;  // output column
  int sub = tid >> 7;    // 0/1: which 8-node group
  if (tid < 128) {
    sAs[tid] = att_s[tid];
    sAd[tid] = att_d[tid];
  }
  for (int i = tid; i < 1024; i += 256) sW[i] = W1[i];
  __syncthreads();
  int head = tcol >> 5, lane = tid & 31;
  int base = ((int)blockIdx.x - histBlocks) * 16 + sub * 8;
  for (int m = 0; m < 8; ++m) {
    int n = base + m;
    if (n >= N) break;  // uniform across the 128-thread subgroup
    float acc = 0.f;
#pragma unroll
    for (int k = 0; k < 8; ++k) acc = fmaf(__ldg(&x[n * 8 + k]), sW[k * 128 + tcol], acc);
    g_h1h[(size_t)n * 128 + tcol] = __float2half(acc);
    float vs = warpsum(acc * sAs[tcol]);
    float vd = warpsum(acc * sAd[tcol]);
    if (lane == 0) {
      ((float*)&g_asrc1[n])[head] = vs;
      ((float*)&g_adst1[n])[head] = vd;
    }
  }
}

// Phase A: per-tile sums (int4 coalesced; +1 per valid node for self loops)
__global__ void scanA_kernel(int N) {
  __shared__ int red[1024];
  int b = blockIdx.x, t = threadIdx.x;
  int base = b * STILE + t * 4;
  int s = 0;
  if (base < N) {
    int4 v = *(const int4*)&g_count[base];  // zero-padded past N
    int vc = N - base; if (vc > 4) vc = 4;
    s = v.x + v.y + v.z + v.w + vc;         // + self loops
  }
  red[t] = s;
  __syncthreads();
  for (int off = 512; off > 0; off >>= 1) {
    if (t < off) red[t] += red[t + off];
    __syncthreads();
  }
  if (t == 0) g_part[b] = red[0];
}

// Phase C: in-tile scan + coalesced int4 writes. The (tiny, nb<=32) tile-sum
// prefix scan is redone locally per block -> no separate scanB launch.
__global__ void scanC_kernel(int N, int nb) {
  __shared__ int sPart[32];
  __shared__ int s[1024];
  int b = blockIdx.x, t = threadIdx.x;
  if (t < 32) {
    int v = (t < nb) ? g_part[t] : 0;
    int incl = v;
#pragma unroll
    for (int off = 1; off < 32; off <<= 1) {
      int u = __shfl_up_sync(0xffffffffu, incl, off);
      if (t >= off) incl += u;
    }
    sPart[t] = incl - v;  // exclusive prefix of tile sums
    if (t == 31 && b == 0) g_rowptr[N] = incl;  // total = E + N
  }
  int base = b * STILE + t * 4;
  int4 v = make_int4(0, 0, 0, 0);
  int vc = 0;
  if (base < N) {
    v = *(const int4*)&g_count[base];
    vc = N - base; if (vc > 4) vc = 4;
  }
  int mysum = v.x + v.y + v.z + v.w + vc;
  s[t] = mysum;
  __syncthreads();
  for (int off = 1; off < 1024; off <<= 1) {
    int u = (t >= off) ? s[t - off] : 0;
    __syncthreads();
    s[t] += u;
    __syncthreads();
  }
  int run = sPart[b] + s[t] - mysum;  // exclusive prefix for this thread
  int4 p;
  p.x = run;
  p.y = p.x + v.x + (vc > 0 ? 1 : 0);
  p.z = p.y + v.y + (vc > 1 ? 1 : 0);
  p.w = p.z + v.z + (vc > 2 ? 1 : 0);
  if (base < N) {
    *(int4*)&g_rowptr[base] = p;
    *(int4*)&g_cursor[base] = p;
  }
}

__global__ void scatter_kernel(const int* __restrict__ srcv,
                               const int* __restrict__ dstv, int E, int N) {
  int i = blockIdx.x * blockDim.x + threadIdx.x;
  if (i < E) {
    int p = atomicAdd(&g_cursor[dstv[i]], 1);
    g_colsrc[p] = srcv[i];
  } else if (i < E + N) {
    int n = i - E;  // self loop
    int p = atomicAdd(&g_cursor[n], 1);
    g_colsrc[p] = n;
  }
}

// ---------------- layer-2 GEMM via HMMA tensor cores ------------------------
__global__ void gemm2_kernel(const float* __restrict__ att_s,
                             const float* __restrict__ att_d, int N) {
  __shared__ __align__(16) __half sA[32 * 128];   // 8KB; reused as C (fp16)
  __shared__ __align__(16) __half sB[128 * 128];  // 32KB (W2 fp16, swizzled)
  __shared__ float4 sAs4[32], sAd4[32];
  int tid = threadIdx.x;  // 256
  int warp = tid >> 5, lane = tid & 31;
  int base = blockIdx.x * 32;

  if (tid < 32) {
    sAs4[tid] = ((const float4*)att_s)[tid];
    sAd4[tid] = ((const float4*)att_d)[tid];
  }

  // load pre-converted W2 (fp16) -> sB swizzled: 2048 chunks of 16B
  for (int idx = tid; idx < 2048; idx += 256) {
    int k = idx >> 4, ch = idx & 15;
    uint4 v = *(const uint4*)(g_W2h + k * 128 + ch * 8);
    *(uint4*)(sB + k * 128 + ((ch ^ (k & 7)) << 3)) = v;
  }
  for (int idx = tid; idx < 512; idx += 256) {
    int r = idx >> 4, ch = idx & 15;
    int node = base + r;
    uint4 v = make_uint4(0u, 0u, 0u, 0u);
    if (node < N) v = *(const uint4*)(g_out1h + (size_t)node * 128 + ch * 8);
    *(uint4*)(sA + r * 128 + ((ch ^ (r & 7)) << 3)) = v;
  }
  __syncthreads();

  int wr = warp & 1;   // M: rows wr*16..+16
  int wc = warp >> 1;  // N: cols wc*32..+32
  int grp = lane >> 3;

  int a_row = wr * 16 + (lane & 7) + ((grp & 1) << 3);
  int b_krow_off = (lane & 7) + ((grp & 1) << 3);
  uint32_t sA_base = smem_u32(sA);
  uint32_t sB_base = smem_u32(sB);

  float d[4][4];
#pragma unroll
  for (int t = 0; t < 4; ++t)
#pragma unroll
    for (int j = 0; j < 4; ++j) d[t][j] = 0.f;

#pragma unroll
  for (int kk = 0; kk < 8; ++kk) {
    int a_ch = kk * 2 + (grp >> 1);
    uint32_t aaddr = sA_base + (uint32_t)(a_row * 256 + ((a_ch ^ (a_row & 7)) << 4));
    uint32_t a0, a1, a2, a3;
    ldsm_x4(a0, a1, a2, a3, aaddr);

    int k_row = kk * 16 + b_krow_off;
    int cb0 = wc * 4 + (grp >> 1);
    uint32_t baddr0 = sB_base + (uint32_t)(k_row * 256 + ((cb0 ^ (k_row & 7)) << 4));
    uint32_t baddr1 = sB_base + (uint32_t)(k_row * 256 + (((cb0 + 2) ^ (k_row & 7)) << 4));
    uint32_t b0, b1, b2, b3, b4, b5, b6, b7;
    ldsm_x4_t(b0, b1, b2, b3, baddr0);
    ldsm_x4_t(b4, b5, b6, b7, baddr1);

    mma16816(d[0][0], d[0][1], d[0][2], d[0][3], a0, a1, a2, a3, b0, b1);
    mma16816(d[1][0], d[1][1], d[1][2], d[1][3], a0, a1, a2, a3, b2, b3);
    mma16816(d[2][0], d[2][1], d[2][2], d[2][3], a0, a1, a2, a3, b4, b5);
    mma16816(d[3][0], d[3][1], d[3][2], d[3][3], a0, a1, a2, a3, b6, b7);
  }
  __syncthreads();

  {
    int crow = wr * 16 + (lane >> 2);
    int ccol0 = wc * 32 + (lane & 3) * 2;
#pragma unroll
    for (int t = 0; t < 4; ++t) {
      int c = ccol0 + t * 8;
      __half2 lo = __floats2half2_rn(d[t][0], d[t][1]);
      __half2 hi = __floats2half2_rn(d[t][2], d[t][3]);
      *(__half2*)(sA + crow * 128 + c) = lo;
      *(__half2*)(sA + (crow + 8) * 128 + c) = hi;
    }
  }
  __syncthreads();

  float4 as = sAs4[lane], ad = sAd4[lane];
  int head = lane >> 3;
#pragma unroll
  for (int m = 0; m < 4; ++m) {
    int r = warp * 4 + m;
    int n = base + r;
    uint2 u = *(uint2*)(sA + r * 128 + lane * 4);
    __half2 p0 = *(__half2*)&u.x;
    __half2 p1 = *(__half2*)&u.y;
    float2 f0 = __half22float2(p0);
    float2 f1 = __half22float2(p1);
    float ts = f0.x * as.x + f0.y * as.y + f1.x * as.z + f1.y * as.w;
    float td = f0.x * ad.x + f0.y * ad.y + f1.x * ad.z + f1.y * ad.w;
    ts += __shfl_xor_sync(0xffffffffu, ts, 1);
    ts += __shfl_xor_sync(0xffffffffu, ts, 2);
    ts += __shfl_xor_sync(0xffffffffu, ts, 4);
    td += __shfl_xor_sync(0xffffffffu, td, 1);
    td += __shfl_xor_sync(0xffffffffu, td, 2);
    td += __shfl_xor_sync(0xffffffffu, td, 4);
    if (n < N) {
      *(uint2*)(g_h2h + (size_t)n * 128 + lane * 4) = u;
      if ((lane & 7) == 0) {
        ((float*)&g_asrc2[n])[head] = ts;
        ((float*)&g_adst2[n])[head] = td;
      }
    }
  }
}

// ---------------- GAT aggregation: warp per dst node, single pass -----------
// Static node schedule (PROVEN best: both sort and work stealing regressed).
// 8-wide gather batches (16-wide spills registers).
__device__ __forceinline__ void acc_h4(const __half* __restrict__ hh, int s,
                                       int lane, float al,
                                       float& ax, float& ay, float& az, float& aw) {
  uint2 u = *(const uint2*)(hh + (size_t)s * 128 + lane * 4);
  __half2 p0 = *(__half2*)&u.x;
  __half2 p1 = *(__half2*)&u.y;
  float2 f0 = __half22float2(p0);
  float2 f1 = __half22float2(p1);
  ax = fmaf(f0.x, al, ax);
  ay = fmaf(f0.y, al, ay);
  az = fmaf(f1.x, al, az);
  aw = fmaf(f1.y, al, aw);
}

__global__ void __launch_bounds__(256)
gat_aggregate_kernel(float* __restrict__ dout,
                     const float* __restrict__ bias,
                     const float* __restrict__ wlin,
                     const float* __restrict__ blin,
                     int N, int mode) {
  int gw = (blockIdx.x * blockDim.x + threadIdx.x) >> 5;
  int lane = threadIdx.x & 31;
  if (gw >= N) return;

  const __half* hh    = (mode == 0) ? g_h1h : g_h2h;
  const float*  asrcf = (const float*)((mode == 0) ? g_asrc1 : g_asrc2);
  const float*  adstf = (const float*)((mode == 0) ? g_adst1 : g_adst2);

  int rs = g_rowptr[gw], re = g_rowptr[gw + 1];
  int head = lane >> 3;  // lane owns channels [4*lane, 4*lane+4)
  float adh = __ldg(&adstf[gw * 4 + head]);

  float ax = 0.f, ay = 0.f, az = 0.f, aw = 0.f, den = 0.f;

  for (int c = rs; c < re; c += 32) {
    int cnt = re - c; if (cnt > 32) cnt = 32;
    int idx = c + lane;
    int sv = g_colsrc[idx < re ? idx : re - 1];  // coalesced prefetch
    int j = 0;
    for (; j + 8 <= cnt; j += 8) {
      int s[8];
#pragma unroll
      for (int u = 0; u < 8; ++u) s[u] = __shfl_sync(0xffffffffu, sv, j + u);
      float av[8];
#pragma unroll
      for (int u = 0; u < 8; ++u) av[u] = __ldg(&asrcf[s[u] * 4 + head]);
      float al[8];
#pragma unroll
      for (int u = 0; u < 8; ++u) al[u] = __expf(lrelu(av[u] + adh));
#pragma unroll
      for (int u = 0; u < 8; ++u) {
        acc_h4(hh, s[u], lane, al[u], ax, ay, az, aw);
        den += al[u];
      }
    }
    for (; j < cnt; ++j) {
      int s0 = __shfl_sync(0xffffffffu, sv, j);
      float al = __expf(lrelu(__ldg(&asrcf[s0 * 4 + head]) + adh));
      acc_h4(hh, s0, lane, al, ax, ay, az, aw);
      den += al;
    }
  }
  float rd = 1.0f / den;  // den identical across each head's 8 lanes
  ax *= rd; ay *= rd; az *= rd; aw *= rd;

  if (mode == 0) {
    float4 b = ((const float4*)bias)[lane];
    __half2 lo = __floats2half2_rn(fmaxf(ax + b.x, 0.f), fmaxf(ay + b.y, 0.f));
    __half2 hi = __floats2half2_rn(fmaxf(az + b.z, 0.f), fmaxf(aw + b.w, 0.f));
    uint2 packed;
    packed.x = *(unsigned*)&lo;
    packed.y = *(unsigned*)&hi;
    *(uint2*)(g_out1h + (size_t)gw * 128 + lane * 4) = packed;  // device symbol
  } else {
    ax += __shfl_xor_sync(0xffffffffu, ax, 8);
    ax += __shfl_xor_sync(0xffffffffu, ax, 16);
    ay += __shfl_xor_sync(0xffffffffu, ay, 8);
    ay += __shfl_xor_sync(0xffffffffu, ay, 16);
    az += __shfl_xor_sync(0xffffffffu, az, 8);
    az += __shfl_xor_sync(0xffffffffu, az, 16);
    aw += __shfl_xor_sync(0xffffffffu, aw, 8);
    aw += __shfl_xor_sync(0xffffffffu, aw, 16);
    int c0 = (lane & 7) * 4;
    float v0 = fmaxf(ax * 0.25f + bias[c0 + 0], 0.f);
    float v1 = fmaxf(ay * 0.25f + bias[c0 + 1], 0.f);
    float v2 = fmaxf(az * 0.25f + bias[c0 + 2], 0.f);
    float v3 = fmaxf(aw * 0.25f + bias[c0 + 3], 0.f);
    float p = v0 * wlin[c0] + v1 * wlin[c0 + 1] + v2 * wlin[c0 + 2] + v3 * wlin[c0 + 3];
    p += __shfl_xor_sync(0xffffffffu, p, 1);
    p += __shfl_xor_sync(0xffffffffu, p, 2);
    p += __shfl_xor_sync(0xffffffffu, p, 4);
    if (lane == 0) dout[gw] = p + blin[0];
  }
}

// ---------------- launch -----------------------------------------------------
extern "C" void kernel_launch(void* const* d_in, const int* in_sizes, int n_in,
                              void* d_out, int out_size) {
  const float* x    = (const float*)d_in[0];
  const int*   ei   = (const int*)d_in[1];
  const float* W1   = (const float*)d_in[2];
  const float* as1  = (const float*)d_in[3];
  const float* ad1  = (const float*)d_in[4];
  const float* b1   = (const float*)d_in[5];
  const float* W2   = (const float*)d_in[6];
  const float* as2  = (const float*)d_in[7];
  const float* ad2  = (const float*)d_in[8];
  const float* b2   = (const float*)d_in[9];
  const float* wlin = (const float*)d_in[10];
  const float* blin = (const float*)d_in[11];

  int N = in_sizes[0] / 8;
  int E = in_sizes[1] / 2;
  const int* srcv = ei;
  const int* dstv = ei + E;
  int ntiles = (N + STILE - 1) / STILE;
  int histBlocks = (E + 255) / 256;
  int gemm1Blocks = (N + 15) / 16;

  // CSR build, with gemm1 overlapped into the histogram launch;
  // W2 fp16 pre-conversion rides in the zero-fill launch.
  zero_count_kernel<<<(N / 4 + 256) / 256, 256>>>(W2, N);
  hist_gemm1_kernel<<<histBlocks + gemm1Blocks, 256>>>(dstv, E, x, W1, as1, ad1,
                                                       N, histBlocks);
  scanA_kernel<<<ntiles, 1024>>>(N);
  scanC_kernel<<<ntiles, 1024>>>(N, ntiles);  // scanB folded in
  scatter_kernel<<<(E + N + 255) / 256, 256>>>(srcv, dstv, E, N);

  // layer 1 aggregate (writes g_out1h internally)
  gat_aggregate_kernel<<<(N + 7) / 8, 256>>>((float*)d_out, b1, nullptr, nullptr, N, 0);

  // layer 2: tensor-core GEMM + fused epilogues
  gemm2_kernel<<<(N + 31) / 32, 256>>>(as2, ad2, N);
  gat_aggregate_kernel<<<(N + 7) / 8, 256>>>((float*)d_out, b2, wlin, blin, N, 1);
}